// round 6
// baseline (speedup 1.0000x reference)
#include <cuda_runtime.h>
#include <cuda_fp16.h>
#include <math.h>
#include <stdint.h>

#define T 1024
#define HD 1024
#define FD 1024
#define NE 32
#define TOPK 4
#define NPAIR (T*TOPK)

#define BM 128
#define BN 128
#define BK 32
#define NIT 32
#define MT_MAX 64

#define SAW 20                 // uint32 words per smem row (32 halves + 8 pad)
#define TILE_WORDS (128*SAW)   // 2560 words = 10240 B per tile
#define STAGE_WORDS (2*TILE_WORDS)

// ---------------- scratch ----------------
__device__ float g_t[T*HD];
__device__ float g_wt[NPAIR];
__device__ int   g_eid[NPAIR];
__device__ int   g_cnt[NE];
__device__ int   g_pos[NE];
__device__ int   g_off[NE+1];
__device__ int   g_perm[NPAIR];
__device__ int   g_tile_e[MT_MAX];
__device__ int   g_tile_row[MT_MAX];
__device__ int   g_tile_cnt[MT_MAX];
__device__ int   g_numtiles;
__device__ float g_act[(size_t)NPAIR*FD];

// ---------------- helpers ----------------
__device__ __forceinline__ uint32_t pack_h2(float a, float b){
    __half2 h = __floats2half2_rn(a, b);
    return *reinterpret_cast<uint32_t*>(&h);
}
__device__ __forceinline__ void mma16(float* d, const uint32_t* a, const uint32_t* b){
    asm volatile("mma.sync.aligned.m16n8k16.row.col.f32.f16.f16.f32 "
                 "{%0,%1,%2,%3},{%4,%5,%6,%7},{%8,%9},{%0,%1,%2,%3};\n"
                 : "+f"(d[0]), "+f"(d[1]), "+f"(d[2]), "+f"(d[3])
                 : "r"(a[0]), "r"(a[1]), "r"(a[2]), "r"(a[3]),
                   "r"(b[0]), "r"(b[1]));
}

// ---------------- init ----------------
__global__ void init_kernel(const float* __restrict__ x, float* __restrict__ out){
    int i = blockIdx.x*blockDim.x + threadIdx.x;
    if (i < T*HD) out[i] = x[i];
    if (i < NE) { g_cnt[i] = 0; g_pos[i] = 0; }
}

// ---------------- rmsnorm + gate + top-4 + softmax ----------------
__global__ void route_kernel(const float* __restrict__ x,
                             const float* __restrict__ nscale,
                             const float* __restrict__ gw,
                             const float* __restrict__ gb){
    int t  = blockIdx.x;
    int tx = threadIdx.x;
    __shared__ float sT[HD];
    __shared__ float sred[256];
    __shared__ float slog[NE];
    const float* xr = x + (size_t)t*HD;

    float ss = 0.f;
    for (int i = tx; i < HD; i += 256){ float v = xr[i]; sT[i] = v; ss += v*v; }
    sred[tx] = ss; __syncthreads();
    for (int s = 128; s > 0; s >>= 1){ if (tx < s) sred[tx] += sred[tx+s]; __syncthreads(); }
    float r = rsqrtf(sred[0]/(float)HD + 1e-5f);
    __syncthreads();
    for (int i = tx; i < HD; i += 256){
        float v = sT[i]*r*nscale[i];
        sT[i] = v;
        g_t[(size_t)t*HD + i] = v;
    }
    __syncthreads();

    int e  = (tx>>5)*4 + ((tx&31)>>3);
    int li = tx & 7;
    const float* gwr = gw + (size_t)e*HD;
    float p = 0.f;
    for (int i = li; i < HD; i += 8) p += sT[i]*gwr[i];
    p += __shfl_down_sync(0xffffffffu, p, 4, 8);
    p += __shfl_down_sync(0xffffffffu, p, 2, 8);
    p += __shfl_down_sync(0xffffffffu, p, 1, 8);
    if (li == 0) slog[e] = p + gb[e];
    __syncthreads();

    if (tx == 0){
        float l[NE];
        #pragma unroll
        for (int i = 0; i < NE; i++) l[i] = slog[i];
        float v[TOPK]; int id[TOPK];
        #pragma unroll
        for (int k = 0; k < TOPK; k++){
            float best = -1e30f; int bi = 0;
            for (int i = 0; i < NE; i++) if (l[i] > best){ best = l[i]; bi = i; }
            v[k] = best; id[k] = bi; l[bi] = -1e30f;
        }
        float m = v[0], s = 0.f, w4[TOPK];
        #pragma unroll
        for (int k = 0; k < TOPK; k++){ w4[k] = expf(v[k]-m); s += w4[k]; }
        float inv = 1.f/s;
        #pragma unroll
        for (int k = 0; k < TOPK; k++){
            int pr = t*TOPK + k;
            g_wt[pr]  = w4[k]*inv;
            g_eid[pr] = id[k];
            atomicAdd(&g_cnt[id[k]], 1);
        }
    }
}

// ---------------- offsets + tiles ----------------
__global__ void scan_kernel(){
    int off = 0, nt = 0;
    for (int e = 0; e < NE; e++){
        g_off[e] = off;
        int c = g_cnt[e];
        for (int r2 = 0; r2 < c; r2 += BM){
            g_tile_e[nt]   = e;
            g_tile_row[nt] = off + r2;
            g_tile_cnt[nt] = min(BM, c - r2);
            nt++;
        }
        off += c;
    }
    g_off[NE]  = off;
    g_numtiles = nt;
}

__global__ void scatter_kernel(){
    int p = blockIdx.x*blockDim.x + threadIdx.x;
    if (p < NPAIR){
        int e = g_eid[p];
        int pos = g_off[e] + atomicAdd(&g_pos[e], 1);
        g_perm[pos] = p;
    }
}

// ============ fp16 mma.sync grouped GEMM mainloop ============
struct Frag { float acc[4][4][4]; };

__device__ __forceinline__ void gemm_mainloop(
    uint32_t* dsm, const int* sPair,
    const float* __restrict__ Asrc, int a_is_token,
    const float* __restrict__ W,
    Frag& fr, int tx)
{
    int lane = tx & 31, w = tx >> 5;
    int seg  = lane & 7;
    int rbase = w*16 + (lane >> 3);     // + 4*p, p=0..3

    int g  = lane >> 2, t4 = lane & 3;
    int wm = w & 1, wn = w >> 1;
    int m0b = wm*64, n0b = wn*32;

    #pragma unroll
    for (int mt = 0; mt < 4; mt++)
        #pragma unroll
        for (int nt = 0; nt < 4; nt++)
            #pragma unroll
            for (int i = 0; i < 4; i++) fr.acc[mt][nt][i] = 0.f;

    // precompute per-row A source pointers
    const float* aptr[4];
    int avalid[4];
    const float* bptr[4];
    #pragma unroll
    for (int p = 0; p < 4; p++){
        int row = rbase + p*4;
        int pr  = sPair[row];
        avalid[p] = (pr >= 0);
        long arow = a_is_token ? (long)(pr >> 2) : (long)pr;
        aptr[p] = Asrc + (avalid[p] ? arow*1024 : 0) + seg*4;
        bptr[p] = W + (size_t)row*1024 + seg*4;
    }

    float4 Ar[4], Br[4];

    // prologue: load iter 0
    #pragma unroll
    for (int p = 0; p < 4; p++){
        Ar[p] = avalid[p] ? *(const float4*)(aptr[p]) : make_float4(0,0,0,0);
        Br[p] = *(const float4*)(bptr[p]);
    }
    {   // store stage 0
        uint32_t* A = dsm;
        uint32_t* B = dsm + TILE_WORDS;
        #pragma unroll
        for (int p = 0; p < 4; p++){
            int row = rbase + p*4;
            *(uint2*)&A[row*SAW + seg*2] =
                make_uint2(pack_h2(Ar[p].x, Ar[p].y), pack_h2(Ar[p].z, Ar[p].w));
            *(uint2*)&B[row*SAW + seg*2] =
                make_uint2(pack_h2(Br[p].x, Br[p].y), pack_h2(Br[p].z, Br[p].w));
        }
    }
    __syncthreads();

    for (int it = 0; it < NIT; it++){
        // issue LDG for next iteration early
        if (it + 1 < NIT){
            int kk = (it+1)*BK;
            #pragma unroll
            for (int p = 0; p < 4; p++){
                Ar[p] = avalid[p] ? *(const float4*)(aptr[p] + kk) : make_float4(0,0,0,0);
                Br[p] = *(const float4*)(bptr[p] + kk);
            }
        }

        const uint32_t* A32 = dsm + (it & 1)*STAGE_WORDS;
        const uint32_t* B32 = A32 + TILE_WORDS;
        #pragma unroll
        for (int ks = 0; ks < 2; ks++){
            uint32_t afr[4][4], bfr[4][2];
            int ko = ks*8 + t4;
            #pragma unroll
            for (int mt = 0; mt < 4; mt++){
                int r = m0b + mt*16 + g;
                afr[mt][0] = A32[r*SAW + ko];
                afr[mt][1] = A32[(r+8)*SAW + ko];
                afr[mt][2] = A32[r*SAW + ko + 4];
                afr[mt][3] = A32[(r+8)*SAW + ko + 4];
            }
            #pragma unroll
            for (int nt = 0; nt < 4; nt++){
                int c = n0b + nt*8 + g;
                bfr[nt][0] = B32[c*SAW + ko];
                bfr[nt][1] = B32[c*SAW + ko + 4];
            }
            #pragma unroll
            for (int mt = 0; mt < 4; mt++)
                #pragma unroll
                for (int nt = 0; nt < 4; nt++)
                    mma16(fr.acc[mt][nt], afr[mt], bfr[nt]);
        }

        // convert + store next stage
        if (it + 1 < NIT){
            uint32_t* A = dsm + ((it+1) & 1)*STAGE_WORDS;
            uint32_t* B = A + TILE_WORDS;
            #pragma unroll
            for (int p = 0; p < 4; p++){
                int row = rbase + p*4;
                *(uint2*)&A[row*SAW + seg*2] =
                    make_uint2(pack_h2(Ar[p].x, Ar[p].y), pack_h2(Ar[p].z, Ar[p].w));
                *(uint2*)&B[row*SAW + seg*2] =
                    make_uint2(pack_h2(Br[p].x, Br[p].y), pack_h2(Br[p].z, Br[p].w));
            }
        }
        __syncthreads();
    }
}

// ---------------- mlp1: grouped GEMM + swiglu ----------------
__global__ __launch_bounds__(256) void mlp1_kernel(const float* __restrict__ w1,
                                                   const float* __restrict__ b1){
    int mt_ = blockIdx.x;
    if (mt_ >= g_numtiles) return;
    int e        = g_tile_e[mt_];
    int rowstart = g_tile_row[mt_];
    int rcnt     = g_tile_cnt[mt_];
    int nb       = blockIdx.y;

    __shared__ int   sPair[BM];
    __shared__ float sWgt[BM];
    extern __shared__ uint32_t dsm[];

    int tx = threadIdx.x;
    if (tx < BM){
        int p = (tx < rcnt) ? g_perm[rowstart + tx] : -1;
        sPair[tx] = p;
        sWgt[tx]  = (p >= 0) ? g_wt[p] : 0.f;
    }
    __syncthreads();

    const float* W = w1 + (size_t)e*(2*FD)*HD + (size_t)(nb*BN)*HD;
    Frag fr;
    gemm_mainloop(dsm, sPair, g_t, 1, W, fr, tx);

    int w  = tx >> 5, lane = tx & 31;
    int g  = lane >> 2, t4 = lane & 3;
    int wm = w & 1, wn = w >> 1;
    const float* b1e = b1 + (size_t)e*(2*FD);

    #pragma unroll
    for (int nt = 0; nt < 4; nt++){
        int colb = nb*BN + wn*32 + nt*8 + 2*t4;      // even
        float bg = b1e[colb], bl = b1e[colb+1];
        int f = colb >> 1;
        #pragma unroll
        for (int mt = 0; mt < 4; mt++){
            #pragma unroll
            for (int half = 0; half < 2; half++){
                int row = wm*64 + mt*16 + g + half*8;
                int p = sPair[row];
                if (p < 0) continue;
                float wg = sWgt[row];
                float d0 = fr.acc[mt][nt][2*half+0] + bg;
                float d1 = fr.acc[mt][nt][2*half+1] + bl;
                float glu = fminf(d0, 7.0f);
                float lin = fminf(fmaxf(d1, -7.0f), 7.0f);
                float sg  = 1.f/(1.f + expf(-1.702f*glu));
                g_act[(size_t)p*FD + f] = glu*sg*(lin + 1.f)*wg;
            }
        }
    }
}

// ---------------- mlp2: grouped GEMM + scatter-add ----------------
__global__ __launch_bounds__(256) void mlp2_kernel(const float* __restrict__ w2,
                                                   const float* __restrict__ b2,
                                                   float* __restrict__ out){
    int mt_ = blockIdx.x;
    if (mt_ >= g_numtiles) return;
    int e        = g_tile_e[mt_];
    int rowstart = g_tile_row[mt_];
    int rcnt     = g_tile_cnt[mt_];
    int nb       = blockIdx.y;

    __shared__ int   sPair[BM];
    __shared__ float sWgt[BM];
    extern __shared__ uint32_t dsm[];

    int tx = threadIdx.x;
    if (tx < BM){
        int p = (tx < rcnt) ? g_perm[rowstart + tx] : -1;
        sPair[tx] = p;
        sWgt[tx]  = (p >= 0) ? g_wt[p] : 0.f;
    }
    __syncthreads();

    const float* W = w2 + (size_t)e*HD*FD + (size_t)(nb*BN)*FD;
    Frag fr;
    gemm_mainloop(dsm, sPair, g_act, 0, W, fr, tx);

    int w  = tx >> 5, lane = tx & 31;
    int g  = lane >> 2, t4 = lane & 3;
    int wm = w & 1, wn = w >> 1;
    const float* b2e = b2 + (size_t)e*HD;

    #pragma unroll
    for (int nt = 0; nt < 4; nt++){
        int colb = nb*BN + wn*32 + nt*8 + 2*t4;
        float bb0 = b2e[colb], bb1 = b2e[colb+1];
        #pragma unroll
        for (int mt = 0; mt < 4; mt++){
            #pragma unroll
            for (int half = 0; half < 2; half++){
                int row = wm*64 + mt*16 + g + half*8;
                int p = sPair[row];
                if (p < 0) continue;
                int tok = p >> 2;
                float wg = sWgt[row];
                float* o = out + (size_t)tok*HD + colb;
                atomicAdd(o,     fr.acc[mt][nt][2*half+0] + wg*bb0);
                atomicAdd(o + 1, fr.acc[mt][nt][2*half+1] + wg*bb1);
            }
        }
    }
}

// ---------------- launch ----------------
extern "C" void kernel_launch(void* const* d_in, const int* in_sizes, int n_in,
                              void* d_out, int out_size){
    const float* x      = (const float*)d_in[0];
    const float* nscale = (const float*)d_in[1];
    const float* gw     = (const float*)d_in[2];
    const float* gb     = (const float*)d_in[3];
    const float* w1     = (const float*)d_in[4];
    const float* b1     = (const float*)d_in[5];
    const float* w2     = (const float*)d_in[6];
    const float* b2     = (const float*)d_in[7];
    float* out = (float*)d_out;

    const int smem_bytes = 2*STAGE_WORDS*4;     // 40960
    static int configured = 0;
    if (!configured){
        cudaFuncSetAttribute(mlp1_kernel, cudaFuncAttributeMaxDynamicSharedMemorySize, smem_bytes);
        cudaFuncSetAttribute(mlp2_kernel, cudaFuncAttributeMaxDynamicSharedMemorySize, smem_bytes);
        configured = 1;
    }

    init_kernel   <<<(T*HD + 255)/256, 256>>>(x, out);
    route_kernel  <<<T, 256>>>(x, nscale, gw, gb);
    scan_kernel   <<<1, 1>>>();
    scatter_kernel<<<(NPAIR + 255)/256, 256>>>();
    mlp1_kernel   <<<dim3(MT_MAX, (2*FD)/BN), 256, smem_bytes>>>(w1, b1);
    mlp2_kernel   <<<dim3(MT_MAX, HD/BN),     256, smem_bytes>>>(w2, b2, out);
}

// round 10
// speedup vs baseline: 1.7345x; 1.7345x over previous
#include <cuda_runtime.h>
#include <cuda_fp16.h>
#include <math.h>
#include <stdint.h>

#define T 1024
#define HD 1024
#define FD 1024
#define NE 32
#define TOPK 4
#define NPAIR (T*TOPK)

#define BM 128
#define BN 128
#define BK 32                 // halves per iteration
#define NIT 32
#define MT_MAX 64

#define ROWB 80               // padded smem row stride (bytes) for 64B rows
#define TILE_B (128*ROWB)     // 10240 B
#define STAGE_B (2*TILE_B)    // A + B = 20480 B
#define NSTAGE 4

#define W1F (32*2048*1024)    // floats in w1
#define TWF (W1F + 32*1024*1024)

// ---------------- scratch ----------------
__device__ __align__(16) __half g_wh[TWF];        // fp16 w1 | w2
__device__ __align__(16) __half g_th[T*HD];       // rmsnormed tokens fp16
__device__ __align__(16) __half g_acth[(size_t)NPAIR*FD];
__device__ float g_wt[NPAIR];
__device__ int   g_eid[NPAIR];
__device__ int   g_cnt[NE];
__device__ int   g_pos[NE];
__device__ int   g_off[NE+1];
__device__ int   g_perm[NPAIR];
__device__ int   g_tile_e[MT_MAX];
__device__ int   g_tile_row[MT_MAX];
__device__ int   g_tile_cnt[MT_MAX];
__device__ int   g_numtiles;

// ---------------- helpers ----------------
__device__ __forceinline__ uint32_t pack_h2(float a, float b){
    __half2 h = __floats2half2_rn(a, b);
    return *reinterpret_cast<uint32_t*>(&h);
}
__device__ __forceinline__ void cp_async16(unsigned saddr, const void* g, int sz){
    asm volatile("cp.async.cg.shared.global [%0], [%1], 16, %2;\n"
                 :: "r"(saddr), "l"(g), "r"(sz));
}
__device__ __forceinline__ void cp_commit(){ asm volatile("cp.async.commit_group;\n"); }
template<int N>
__device__ __forceinline__ void cp_wait(){ asm volatile("cp.async.wait_group %0;\n"::"n"(N)); }
__device__ __forceinline__ void ldm_x4(uint32_t* r, uint32_t addr){
    asm volatile("ldmatrix.sync.aligned.m8n8.x4.shared.b16 {%0,%1,%2,%3}, [%4];"
                 : "=r"(r[0]), "=r"(r[1]), "=r"(r[2]), "=r"(r[3]) : "r"(addr));
}
__device__ __forceinline__ void mma16(float* d, const uint32_t* a, const uint32_t* b){
    asm volatile("mma.sync.aligned.m16n8k16.row.col.f32.f16.f16.f32 "
                 "{%0,%1,%2,%3},{%4,%5,%6,%7},{%8,%9},{%0,%1,%2,%3};\n"
                 : "+f"(d[0]), "+f"(d[1]), "+f"(d[2]), "+f"(d[3])
                 : "r"(a[0]), "r"(a[1]), "r"(a[2]), "r"(a[3]),
                   "r"(b[0]), "r"(b[1]));
}

// ---------------- weight conversion fp32 -> fp16 ----------------
__global__ void convert_kernel(const float* __restrict__ w1, const float* __restrict__ w2){
    size_t stride = (size_t)gridDim.x*blockDim.x*4;
    for (size_t i = ((size_t)blockIdx.x*blockDim.x + threadIdx.x)*4; i < TWF; i += stride){
        const float* src = (i < W1F) ? (w1 + i) : (w2 + (i - W1F));
        float4 v = *(const float4*)src;
        uint2 o = make_uint2(pack_h2(v.x, v.y), pack_h2(v.z, v.w));
        *(uint2*)(g_wh + i) = o;
    }
}

// ---------------- init ----------------
__global__ void init_kernel(const float* __restrict__ x, float* __restrict__ out){
    int i = blockIdx.x*blockDim.x + threadIdx.x;
    if (i < T*HD) out[i] = x[i];
    if (i < NE) { g_cnt[i] = 0; g_pos[i] = 0; }
}

// ---------------- rmsnorm + gate + top-4 + softmax ----------------
__global__ void route_kernel(const float* __restrict__ x,
                             const float* __restrict__ nscale,
                             const float* __restrict__ gw,
                             const float* __restrict__ gb){
    int t  = blockIdx.x;
    int tx = threadIdx.x;
    __shared__ float sT[HD];
    __shared__ float sred[256];
    __shared__ float slog[NE];
    const float* xr = x + (size_t)t*HD;

    float ss = 0.f;
    for (int i = tx; i < HD; i += 256){ float v = xr[i]; sT[i] = v; ss += v*v; }
    sred[tx] = ss; __syncthreads();
    for (int s = 128; s > 0; s >>= 1){ if (tx < s) sred[tx] += sred[tx+s]; __syncthreads(); }
    float r = rsqrtf(sred[0]/(float)HD + 1e-5f);
    __syncthreads();
    for (int i = tx; i < HD; i += 256){
        float v = sT[i]*r*nscale[i];
        sT[i] = v;
        g_th[(size_t)t*HD + i] = __float2half_rn(v);
    }
    __syncthreads();

    int e  = (tx>>5)*4 + ((tx&31)>>3);
    int li = tx & 7;
    const float* gwr = gw + (size_t)e*HD;
    float p = 0.f;
    for (int i = li; i < HD; i += 8) p += sT[i]*gwr[i];
    p += __shfl_down_sync(0xffffffffu, p, 4, 8);
    p += __shfl_down_sync(0xffffffffu, p, 2, 8);
    p += __shfl_down_sync(0xffffffffu, p, 1, 8);
    if (li == 0) slog[e] = p + gb[e];
    __syncthreads();

    if (tx == 0){
        float l[NE];
        #pragma unroll
        for (int i = 0; i < NE; i++) l[i] = slog[i];
        float v[TOPK]; int id[TOPK];
        #pragma unroll
        for (int k = 0; k < TOPK; k++){
            float best = -1e30f; int bi = 0;
            for (int i = 0; i < NE; i++) if (l[i] > best){ best = l[i]; bi = i; }
            v[k] = best; id[k] = bi; l[bi] = -1e30f;
        }
        float m = v[0], s = 0.f, w4[TOPK];
        #pragma unroll
        for (int k = 0; k < TOPK; k++){ w4[k] = expf(v[k]-m); s += w4[k]; }
        float inv = 1.f/s;
        #pragma unroll
        for (int k = 0; k < TOPK; k++){
            int pr = t*TOPK + k;
            g_wt[pr]  = w4[k]*inv;
            g_eid[pr] = id[k];
            atomicAdd(&g_cnt[id[k]], 1);
        }
    }
}

// ---------------- offsets + tiles ----------------
__global__ void scan_kernel(){
    int off = 0, nt = 0;
    for (int e = 0; e < NE; e++){
        g_off[e] = off;
        int c = g_cnt[e];
        for (int r2 = 0; r2 < c; r2 += BM){
            g_tile_e[nt]   = e;
            g_tile_row[nt] = off + r2;
            g_tile_cnt[nt] = min(BM, c - r2);
            nt++;
        }
        off += c;
    }
    g_off[NE]  = off;
    g_numtiles = nt;
}

__global__ void scatter_kernel(){
    int p = blockIdx.x*blockDim.x + threadIdx.x;
    if (p < NPAIR){
        int e = g_eid[p];
        int pos = g_off[e] + atomicAdd(&g_pos[e], 1);
        g_perm[pos] = p;
    }
}

// ============ fp16 cp.async + ldmatrix grouped GEMM mainloop ============
struct Frag { float acc[4][4][4]; };

__device__ __forceinline__ void gemm_mainloop(
    uint32_t smem0, const int* sPair,
    const __half* __restrict__ Asrc, int a_is_token,
    const __half* __restrict__ W,
    Frag& fr, int tx)
{
    int lane = tx & 31, w = tx >> 5;
    int wm = w & 1, wn = w >> 1;
    int m0b = wm*64, n0b = wn*32;

    #pragma unroll
    for (int mt = 0; mt < 4; mt++)
        #pragma unroll
        for (int nt = 0; nt < 4; nt++)
            #pragma unroll
            for (int i = 0; i < 4; i++) fr.acc[mt][nt][i] = 0.f;

    // per-thread fill assignment: 4 chunks of 16B (A: idx<512, B: idx>=512)
    const __half* srcp[4];
    uint32_t dst0[4];
    int      szv[4];
    #pragma unroll
    for (int i = 0; i < 4; i++){
        int idx = tx + i*256;
        if (idx < 512){
            int row = idx >> 2, c = idx & 3;
            int p = sPair[row];
            int valid = (p >= 0);
            long arow = a_is_token ? (long)(p >> 2) : (long)p;
            srcp[i] = Asrc + (valid ? arow*1024 : 0) + c*8;
            dst0[i] = smem0 + row*ROWB + c*16;
            szv[i]  = valid ? 16 : 0;
        } else {
            int bidx = idx - 512;
            int row = bidx >> 2, c = bidx & 3;
            srcp[i] = W + (size_t)row*1024 + c*8;
            dst0[i] = smem0 + TILE_B + row*ROWB + c*16;
            szv[i]  = 16;
        }
    }

    // ldmatrix base addresses
    // A: row = m0 + (lane&15), chunk = lane>>4  (+2*kstep)
    uint32_t aAddr = smem0 + (m0b + (lane & 15))*ROWB + (lane >> 4)*16;
    // B: row = n0 + (lane&7), chunk = lane>>3
    uint32_t bAddr = smem0 + TILE_B + (n0b + (lane & 7))*ROWB + (lane >> 3)*16;

    // prologue: fill stages 0..2
    #pragma unroll
    for (int f = 0; f < NSTAGE-1; f++){
        #pragma unroll
        for (int i = 0; i < 4; i++)
            cp_async16(dst0[i] + f*STAGE_B, srcp[i] + f*BK, szv[i]);
        cp_commit();
    }

    for (int it = 0; it < NIT; it++){
        cp_wait<NSTAGE-2>();
        __syncthreads();

        uint32_t off = (it & (NSTAGE-1))*STAGE_B;
        uint32_t bfr[4][4];
        #pragma unroll
        for (int nt = 0; nt < 4; nt++)
            ldm_x4(bfr[nt], bAddr + off + nt*8*ROWB);
        #pragma unroll
        for (int ks = 0; ks < 2; ks++){
            #pragma unroll
            for (int mt = 0; mt < 4; mt++){
                uint32_t afr[4];
                ldm_x4(afr, aAddr + off + mt*16*ROWB + ks*32);
                #pragma unroll
                for (int nt = 0; nt < 4; nt++)
                    mma16(fr.acc[mt][nt], afr, &bfr[nt][ks*2]);
            }
        }

        int f = it + NSTAGE - 1;
        if (f < NIT){
            uint32_t doff = (f & (NSTAGE-1))*STAGE_B;
            #pragma unroll
            for (int i = 0; i < 4; i++)
                cp_async16(dst0[i] + doff, srcp[i] + f*BK, szv[i]);
        }
        cp_commit();     // unconditional: keeps group accounting exact
    }
}

// ---------------- mlp1: grouped GEMM + swiglu ----------------
__global__ __launch_bounds__(256, 2) void mlp1_kernel(const float* __restrict__ b1){
    int mt_ = blockIdx.x;
    if (mt_ >= g_numtiles) return;
    int e        = g_tile_e[mt_];
    int rowstart = g_tile_row[mt_];
    int rcnt     = g_tile_cnt[mt_];
    int nb       = blockIdx.y;

    __shared__ int   sPair[BM];
    __shared__ float sWgt[BM];
    extern __shared__ char dsm[];
    uint32_t smem0 = (uint32_t)__cvta_generic_to_shared(dsm);

    int tx = threadIdx.x;
    if (tx < BM){
        int p = (tx < rcnt) ? g_perm[rowstart + tx] : -1;
        sPair[tx] = p;
        sWgt[tx]  = (p >= 0) ? g_wt[p] : 0.f;
    }
    __syncthreads();

    const __half* W = g_wh + (size_t)e*(2*FD)*HD + (size_t)(nb*BN)*HD;
    Frag fr;
    gemm_mainloop(smem0, sPair, g_th, 1, W, fr, tx);

    int w  = tx >> 5, lane = tx & 31;
    int g  = lane >> 2, t4 = lane & 3;
    int wm = w & 1, wn = w >> 1;
    const float* b1e = b1 + (size_t)e*(2*FD);

    #pragma unroll
    for (int nt = 0; nt < 4; nt++){
        int colb = nb*BN + wn*32 + nt*8 + 2*t4;      // even
        float bg = b1e[colb], bl = b1e[colb+1];
        int f = colb >> 1;
        #pragma unroll
        for (int mt = 0; mt < 4; mt++){
            #pragma unroll
            for (int half = 0; half < 2; half++){
                int row = wm*64 + mt*16 + g + half*8;
                int p = sPair[row];
                if (p < 0) continue;
                float wg = sWgt[row];
                float d0 = fr.acc[mt][nt][2*half+0] + bg;
                float d1 = fr.acc[mt][nt][2*half+1] + bl;
                float glu = fminf(d0, 7.0f);
                float lin = fminf(fmaxf(d1, -7.0f), 7.0f);
                float sg  = 1.f/(1.f + expf(-1.702f*glu));
                g_acth[(size_t)p*FD + f] = __float2half_rn(glu*sg*(lin + 1.f)*wg);
            }
        }
    }
}

// ---------------- mlp2: grouped GEMM + scatter-add ----------------
__global__ __launch_bounds__(256, 2) void mlp2_kernel(const float* __restrict__ b2,
                                                      float* __restrict__ out){
    int mt_ = blockIdx.x;
    if (mt_ >= g_numtiles) return;
    int e        = g_tile_e[mt_];
    int rowstart = g_tile_row[mt_];
    int rcnt     = g_tile_cnt[mt_];
    int nb       = blockIdx.y;

    __shared__ int   sPair[BM];
    __shared__ float sWgt[BM];
    extern __shared__ char dsm[];
    uint32_t smem0 = (uint32_t)__cvta_generic_to_shared(dsm);

    int tx = threadIdx.x;
    if (tx < BM){
        int p = (tx < rcnt) ? g_perm[rowstart + tx] : -1;
        sPair[tx] = p;
        sWgt[tx]  = (p >= 0) ? g_wt[p] : 0.f;
    }
    __syncthreads();

    const __half* W = g_wh + (size_t)W1F + (size_t)e*HD*FD + (size_t)(nb*BN)*FD;
    Frag fr;
    gemm_mainloop(smem0, sPair, g_acth, 0, W, fr, tx);

    int w  = tx >> 5, lane = tx & 31;
    int g  = lane >> 2, t4 = lane & 3;
    int wm = w & 1, wn = w >> 1;
    const float* b2e = b2 + (size_t)e*HD;

    #pragma unroll
    for (int nt = 0; nt < 4; nt++){
        int colb = nb*BN + wn*32 + nt*8 + 2*t4;
        float bb0 = b2e[colb], bb1 = b2e[colb+1];
        #pragma unroll
        for (int mt = 0; mt < 4; mt++){
            #pragma unroll
            for (int half = 0; half < 2; half++){
                int row = wm*64 + mt*16 + g + half*8;
                int p = sPair[row];
                if (p < 0) continue;
                int tok = p >> 2;
                float wg = sWgt[row];
                float* o = out + (size_t)tok*HD + colb;
                atomicAdd(o,     fr.acc[mt][nt][2*half+0] + wg*bb0);
                atomicAdd(o + 1, fr.acc[mt][nt][2*half+1] + wg*bb1);
            }
        }
    }
}

// ---------------- launch ----------------
extern "C" void kernel_launch(void* const* d_in, const int* in_sizes, int n_in,
                              void* d_out, int out_size){
    const float* x      = (const float*)d_in[0];
    const float* nscale = (const float*)d_in[1];
    const float* gw     = (const float*)d_in[2];
    const float* gb     = (const float*)d_in[3];
    const float* w1     = (const float*)d_in[4];
    const float* b1     = (const float*)d_in[5];
    const float* w2     = (const float*)d_in[6];
    const float* b2     = (const float*)d_in[7];
    float* out = (float*)d_out;

    const int smem_bytes = NSTAGE*STAGE_B;      // 81920
    static int configured = 0;
    if (!configured){
        cudaFuncSetAttribute(mlp1_kernel, cudaFuncAttributeMaxDynamicSharedMemorySize, smem_bytes);
        cudaFuncSetAttribute(mlp2_kernel, cudaFuncAttributeMaxDynamicSharedMemorySize, smem_bytes);
        configured = 1;
    }

    convert_kernel<<<8192, 256>>>(w1, w2);
    init_kernel   <<<(T*HD + 255)/256, 256>>>(x, out);
    route_kernel  <<<T, 256>>>(x, nscale, gw, gb);
    scan_kernel   <<<1, 1>>>();
    scatter_kernel<<<(NPAIR + 255)/256, 256>>>();
    mlp1_kernel   <<<dim3(MT_MAX, (2*FD)/BN), 256, smem_bytes>>>(b1);
    mlp2_kernel   <<<dim3(MT_MAX, HD/BN),     256, smem_bytes>>>(b2, out);
}

// round 12
// speedup vs baseline: 1.9508x; 1.1247x over previous
#include <cuda_runtime.h>
#include <cuda_fp16.h>
#include <math.h>
#include <stdint.h>

#define T 1024
#define HD 1024
#define FD 1024
#define NE 32
#define TOPK 4
#define NPAIR (T*TOPK)

#define BM 128
#define BN 128
#define BK 32                 // K elements per iteration (halves for A, floats for B)
#define NIT 32
#define MT_MAX 64

#define A_ROWB 80             // A smem row stride bytes (64B data + pad)
#define B_ROWB 160            // B smem row stride bytes (128B data + pad)
#define A_TILE_B (128*A_ROWB) // 10240
#define B_TILE_B (128*B_ROWB) // 20480
#define STAGE_B (A_TILE_B + B_TILE_B)   // 30720
#define NSTAGE 3

// ---------------- scratch ----------------
__device__ __align__(16) __half g_th[T*HD];
__device__ __align__(16) __half g_acth[(size_t)NPAIR*FD];
__device__ float g_wt[NPAIR];
__device__ int   g_eid[NPAIR];
__device__ int   g_cnt[NE];
__device__ int   g_pos[NE];
__device__ int   g_perm[NPAIR];

// ---------------- helpers ----------------
__device__ __forceinline__ uint32_t pack_h2(float a, float b){
    __half2 h = __floats2half2_rn(a, b);
    return *reinterpret_cast<uint32_t*>(&h);
}
__device__ __forceinline__ void cp_async16(unsigned saddr, const void* g, int sz){
    asm volatile("cp.async.cg.shared.global [%0], [%1], 16, %2;\n"
                 :: "r"(saddr), "l"(g), "r"(sz));
}
__device__ __forceinline__ void cp_commit(){ asm volatile("cp.async.commit_group;\n"); }
template<int N>
__device__ __forceinline__ void cp_wait(){ asm volatile("cp.async.wait_group %0;\n"::"n"(N)); }
__device__ __forceinline__ void ldm_x4(uint32_t* r, uint32_t addr){
    asm volatile("ldmatrix.sync.aligned.m8n8.x4.shared.b16 {%0,%1,%2,%3}, [%4];"
                 : "=r"(r[0]), "=r"(r[1]), "=r"(r[2]), "=r"(r[3]) : "r"(addr));
}
__device__ __forceinline__ float2 lds64(uint32_t a){
    float2 r;
    asm volatile("ld.shared.v2.f32 {%0,%1}, [%2];" : "=f"(r.x), "=f"(r.y) : "r"(a));
    return r;
}
__device__ __forceinline__ void mma16(float* d, const uint32_t* a, const uint32_t* b){
    asm volatile("mma.sync.aligned.m16n8k16.row.col.f32.f16.f16.f32 "
                 "{%0,%1,%2,%3},{%4,%5,%6,%7},{%8,%9},{%0,%1,%2,%3};\n"
                 : "+f"(d[0]), "+f"(d[1]), "+f"(d[2]), "+f"(d[3])
                 : "r"(a[0]), "r"(a[1]), "r"(a[2]), "r"(a[3]),
                   "r"(b[0]), "r"(b[1]));
}

// ---------------- init: zero counters only ----------------
__global__ void init_kernel(){
    int i = threadIdx.x;
    if (i < NE) { g_cnt[i] = 0; g_pos[i] = 0; }
}

// ---------------- rmsnorm + residual copy + gate + top-4 + softmax ----------------
__global__ void route_kernel(const float* __restrict__ x,
                             const float* __restrict__ nscale,
                             const float* __restrict__ gw,
                             const float* __restrict__ gb,
                             float* __restrict__ out){
    int t  = blockIdx.x;
    int tx = threadIdx.x;
    __shared__ float sT[HD];
    __shared__ float sred[256];
    __shared__ float slog[NE];
    const float* xr = x + (size_t)t*HD;
    float* orow = out + (size_t)t*HD;

    float ss = 0.f;
    for (int i = tx; i < HD; i += 256){
        float v = xr[i];
        sT[i] = v;
        orow[i] = v;              // residual init
        ss += v*v;
    }
    sred[tx] = ss; __syncthreads();
    for (int s = 128; s > 0; s >>= 1){ if (tx < s) sred[tx] += sred[tx+s]; __syncthreads(); }
    float r = rsqrtf(sred[0]/(float)HD + 1e-5f);
    __syncthreads();
    for (int i = tx; i < HD; i += 256){
        float v = sT[i]*r*nscale[i];
        sT[i] = v;
        g_th[(size_t)t*HD + i] = __float2half_rn(v);
    }
    __syncthreads();

    int e  = (tx>>5)*4 + ((tx&31)>>3);
    int li = tx & 7;
    const float* gwr = gw + (size_t)e*HD;
    float p = 0.f;
    for (int i = li; i < HD; i += 8) p += sT[i]*gwr[i];
    p += __shfl_down_sync(0xffffffffu, p, 4, 8);
    p += __shfl_down_sync(0xffffffffu, p, 2, 8);
    p += __shfl_down_sync(0xffffffffu, p, 1, 8);
    if (li == 0) slog[e] = p + gb[e];
    __syncthreads();

    if (tx == 0){
        float l[NE];
        #pragma unroll
        for (int i = 0; i < NE; i++) l[i] = slog[i];
        float v[TOPK]; int id[TOPK];
        #pragma unroll
        for (int k = 0; k < TOPK; k++){
            float best = -1e30f; int bi = 0;
            for (int i = 0; i < NE; i++) if (l[i] > best){ best = l[i]; bi = i; }
            v[k] = best; id[k] = bi; l[bi] = -1e30f;
        }
        float m = v[0], s = 0.f, w4[TOPK];
        #pragma unroll
        for (int k = 0; k < TOPK; k++){ w4[k] = expf(v[k]-m); s += w4[k]; }
        float inv = 1.f/s;
        #pragma unroll
        for (int k = 0; k < TOPK; k++){
            int pr = t*TOPK + k;
            g_wt[pr]  = w4[k]*inv;
            g_eid[pr] = id[k];
            atomicAdd(&g_cnt[id[k]], 1);
        }
    }
}

// ---------------- scatter (in-block expert offsets) ----------------
__global__ void scatter_kernel(){
    __shared__ int soff[NE];
    if (threadIdx.x == 0){
        int off = 0;
        for (int e = 0; e < NE; e++){ soff[e] = off; off += g_cnt[e]; }
    }
    __syncthreads();
    int p = blockIdx.x*blockDim.x + threadIdx.x;
    if (p < NPAIR){
        int e = g_eid[p];
        int pos = soff[e] + atomicAdd(&g_pos[e], 1);
        g_perm[pos] = p;
    }
}

// ============ fp16-A / fp32-B grouped GEMM mainloop ============
struct Frag { float acc[4][4][4]; };

__device__ __forceinline__ void gemm_mainloop(
    uint32_t smem0, const int* sPair,
    const __half* __restrict__ Asrc, int a_is_token,
    const float* __restrict__ W,
    Frag& fr, int tx)
{
    int lane = tx & 31, w = tx >> 5;
    int wm = w & 1, wn = w >> 1;
    int m0b = wm*64, n0b = wn*32;

    #pragma unroll
    for (int mt = 0; mt < 4; mt++)
        #pragma unroll
        for (int nt = 0; nt < 4; nt++)
            #pragma unroll
            for (int i = 0; i < 4; i++) fr.acc[mt][nt][i] = 0.f;

    // per-thread fill: 6 chunks of 16B.  chunks 0..511: A, 512..1535: B
    const char* srcp[6];
    uint32_t    dst0[6];
    int         szv[6];
    int         stepb[6];
    #pragma unroll
    for (int i = 0; i < 6; i++){
        int idx = tx + i*256;
        if (idx < 512){
            int row = idx >> 2, c = idx & 3;
            int p = sPair[row];
            int valid = (p >= 0);
            long arow = a_is_token ? (long)(p >> 2) : (long)p;
            srcp[i]  = (const char*)(Asrc + (valid ? arow*1024 : 0) + c*8);
            dst0[i]  = smem0 + row*A_ROWB + c*16;
            szv[i]   = valid ? 16 : 0;
            stepb[i] = BK*2;              // halves
        } else {
            int bidx = idx - 512;
            int row = bidx >> 3, c = bidx & 7;
            srcp[i]  = (const char*)(W + (size_t)row*1024 + c*4);
            dst0[i]  = smem0 + A_TILE_B + row*B_ROWB + c*16;
            szv[i]   = 16;
            stepb[i] = BK*4;              // floats
        }
    }

    // ldmatrix A base: row = m0 + (lane&15), 16B chunk = lane>>4
    uint32_t aAddr = smem0 + (m0b + (lane & 15))*A_ROWB + (lane >> 4)*16;
    // B fp32 base: n = n0 + (lane>>2), k pair = (lane&3)*2 floats
    uint32_t bAddr = smem0 + A_TILE_B + (n0b + (lane >> 2))*B_ROWB + (lane & 3)*8;

    // prologue: stages 0,1
    #pragma unroll
    for (int f = 0; f < NSTAGE-1; f++){
        #pragma unroll
        for (int i = 0; i < 6; i++)
            cp_async16(dst0[i] + f*STAGE_B, srcp[i] + (size_t)f*stepb[i], szv[i]);
        cp_commit();
    }

    int s_use = 0, s_fill = NSTAGE-1;
    for (int it = 0; it < NIT; it++){
        cp_wait<NSTAGE-2>();
        __syncthreads();

        uint32_t off = s_use*STAGE_B;

        // B fragments: fp32 -> fp16 in register
        uint32_t bfr[4][2][2];
        #pragma unroll
        for (int nt = 0; nt < 4; nt++){
            #pragma unroll
            for (int ks = 0; ks < 2; ks++){
                uint32_t ba = bAddr + off + nt*(8*B_ROWB) + ks*64;
                float2 f0 = lds64(ba);
                float2 f1 = lds64(ba + 32);
                bfr[nt][ks][0] = pack_h2(f0.x, f0.y);
                bfr[nt][ks][1] = pack_h2(f1.x, f1.y);
            }
        }
        #pragma unroll
        for (int ks = 0; ks < 2; ks++){
            #pragma unroll
            for (int mt = 0; mt < 4; mt++){
                uint32_t afr[4];
                ldm_x4(afr, aAddr + off + mt*(16*A_ROWB) + ks*32);
                #pragma unroll
                for (int nt = 0; nt < 4; nt++)
                    mma16(fr.acc[mt][nt], afr, bfr[nt][ks]);
            }
        }

        int f = it + NSTAGE - 1;
        if (f < NIT){
            uint32_t doff = s_fill*STAGE_B;
            #pragma unroll
            for (int i = 0; i < 6; i++)
                cp_async16(dst0[i] + doff, srcp[i] + (size_t)f*stepb[i], szv[i]);
        }
        cp_commit();
        s_use  = (s_use  + 1 == NSTAGE) ? 0 : s_use  + 1;
        s_fill = (s_fill + 1 == NSTAGE) ? 0 : s_fill + 1;
    }
}

// ---------------- per-block tile lookup ----------------
__device__ __forceinline__ void tile_info(int mt_, int* sInfo, int tx){
    if (tx == 0){
        int off = 0, nt = 0, te = -1, trow = 0, tcnt = 0;
        for (int e = 0; e < NE; e++){
            int c = g_cnt[e];
            for (int r = 0; r < c; r += BM){
                if (nt == mt_){ te = e; trow = off + r; tcnt = min(BM, c - r); }
                nt++;
            }
            off += c;
        }
        sInfo[0] = te; sInfo[1] = trow; sInfo[2] = tcnt;
    }
}

// ---------------- mlp1: grouped GEMM + swiglu ----------------
__global__ __launch_bounds__(256, 2) void mlp1_kernel(const float* __restrict__ w1,
                                                      const float* __restrict__ b1){
    __shared__ int   sInfo[3];
    __shared__ int   sPair[BM];
    __shared__ float sWgt[BM];
    extern __shared__ char dsm[];
    uint32_t smem0 = (uint32_t)__cvta_generic_to_shared(dsm);

    int tx = threadIdx.x;
    tile_info(blockIdx.x, sInfo, tx);
    __syncthreads();
    int e = sInfo[0];
    if (e < 0) return;
    int rowstart = sInfo[1], rcnt = sInfo[2];
    int nb = blockIdx.y;

    if (tx < BM){
        int p = (tx < rcnt) ? g_perm[rowstart + tx] : -1;
        sPair[tx] = p;
        sWgt[tx]  = (p >= 0) ? g_wt[p] : 0.f;
    }
    __syncthreads();

    const float* W = w1 + (size_t)e*(2*FD)*HD + (size_t)(nb*BN)*HD;
    Frag fr;
    gemm_mainloop(smem0, sPair, g_th, 1, W, fr, tx);

    int w  = tx >> 5, lane = tx & 31;
    int g  = lane >> 2, t4 = lane & 3;
    int wm = w & 1, wn = w >> 1;
    const float* b1e = b1 + (size_t)e*(2*FD);

    #pragma unroll
    for (int nt = 0; nt < 4; nt++){
        int colb = nb*BN + wn*32 + nt*8 + 2*t4;      // even
        float bg = b1e[colb], bl = b1e[colb+1];
        int f = colb >> 1;
        #pragma unroll
        for (int mt = 0; mt < 4; mt++){
            #pragma unroll
            for (int half = 0; half < 2; half++){
                int row = wm*64 + mt*16 + g + half*8;
                int p = sPair[row];
                if (p < 0) continue;
                float wg = sWgt[row];
                float d0 = fr.acc[mt][nt][2*half+0] + bg;
                float d1 = fr.acc[mt][nt][2*half+1] + bl;
                float glu = fminf(d0, 7.0f);
                float lin = fminf(fmaxf(d1, -7.0f), 7.0f);
                float sg  = 1.f/(1.f + expf(-1.702f*glu));
                g_acth[(size_t)p*FD + f] = __float2half_rn(glu*sg*(lin + 1.f)*wg);
            }
        }
    }
}

// ---------------- mlp2: grouped GEMM + scatter-add ----------------
__global__ __launch_bounds__(256, 2) void mlp2_kernel(const float* __restrict__ w2,
                                                      const float* __restrict__ b2,
                                                      float* __restrict__ out){
    __shared__ int   sInfo[3];
    __shared__ int   sPair[BM];
    __shared__ float sWgt[BM];
    extern __shared__ char dsm[];
    uint32_t smem0 = (uint32_t)__cvta_generic_to_shared(dsm);

    int tx = threadIdx.x;
    tile_info(blockIdx.x, sInfo, tx);
    __syncthreads();
    int e = sInfo[0];
    if (e < 0) return;
    int rowstart = sInfo[1], rcnt = sInfo[2];
    int nb = blockIdx.y;

    if (tx < BM){
        int p = (tx < rcnt) ? g_perm[rowstart + tx] : -1;
        sPair[tx] = p;
        sWgt[tx]  = (p >= 0) ? g_wt[p] : 0.f;
    }
    __syncthreads();

    const float* W = w2 + (size_t)e*HD*FD + (size_t)(nb*BN)*FD;
    Frag fr;
    gemm_mainloop(smem0, sPair, g_acth, 0, W, fr, tx);

    int w  = tx >> 5, lane = tx & 31;
    int g  = lane >> 2, t4 = lane & 3;
    int wm = w & 1, wn = w >> 1;
    const float* b2e = b2 + (size_t)e*HD;

    #pragma unroll
    for (int nt = 0; nt < 4; nt++){
        int colb = nb*BN + wn*32 + nt*8 + 2*t4;
        float bb0 = b2e[colb], bb1 = b2e[colb+1];
        #pragma unroll
        for (int mt = 0; mt < 4; mt++){
            #pragma unroll
            for (int half = 0; half < 2; half++){
                int row = wm*64 + mt*16 + g + half*8;
                int p = sPair[row];
                if (p < 0) continue;
                int tok = p >> 2;
                float wg = sWgt[row];
                float* o = out + (size_t)tok*HD + colb;
                atomicAdd(o,     fr.acc[mt][nt][2*half+0] + wg*bb0);
                atomicAdd(o + 1, fr.acc[mt][nt][2*half+1] + wg*bb1);
            }
        }
    }
}

// ---------------- launch ----------------
extern "C" void kernel_launch(void* const* d_in, const int* in_sizes, int n_in,
                              void* d_out, int out_size){
    const float* x      = (const float*)d_in[0];
    const float* nscale = (const float*)d_in[1];
    const float* gw     = (const float*)d_in[2];
    const float* gb     = (const float*)d_in[3];
    const float* w1     = (const float*)d_in[4];
    const float* b1     = (const float*)d_in[5];
    const float* w2     = (const float*)d_in[6];
    const float* b2     = (const float*)d_in[7];
    float* out = (float*)d_out;

    const int smem_bytes = NSTAGE*STAGE_B;      // 92160
    static int configured = 0;
    if (!configured){
        cudaFuncSetAttribute(mlp1_kernel, cudaFuncAttributeMaxDynamicSharedMemorySize, smem_bytes);
        cudaFuncSetAttribute(mlp2_kernel, cudaFuncAttributeMaxDynamicSharedMemorySize, smem_bytes);
        configured = 1;
    }

    init_kernel   <<<1, 64>>>();
    route_kernel  <<<T, 256>>>(x, nscale, gw, gb, out);
    scatter_kernel<<<(NPAIR + 255)/256, 256>>>();
    mlp1_kernel   <<<dim3(MT_MAX, (2*FD)/BN), 256, smem_bytes>>>(w1, b1);
    mlp2_kernel   <<<dim3(MT_MAX, HD/BN),     256, smem_bytes>>>(w2, b2, out);
}

// round 13
// speedup vs baseline: 1.9662x; 1.0079x over previous
#include <cuda_runtime.h>
#include <cuda_fp16.h>
#include <math.h>
#include <stdint.h>

#define T 1024
#define HD 1024
#define FD 1024
#define NE 32
#define TOPK 4
#define NPAIR (T*TOPK)

#define BM 128
#define BN 128
#define BK 32                 // K elements per iteration (halves for A, floats for B)
#define NIT 32
#define MT_MAX 64

#define A_ROWB 80             // A smem row stride bytes (64B data + pad)
#define B_ROWB 160            // B smem row stride bytes (128B data + pad)
#define A_TILE_B (128*A_ROWB) // 10240
#define B_TILE_B (128*B_ROWB) // 20480
#define STAGE_B (A_TILE_B + B_TILE_B)   // 30720
#define NSTAGE 3

// ---------------- scratch ----------------
__device__ __align__(16) __half g_th[T*HD];
__device__ __align__(16) __half g_acth[(size_t)NPAIR*FD];
__device__ float g_wt[NPAIR];
__device__ int   g_eid[NPAIR];
__device__ int   g_cnt[NE];
__device__ int   g_pos[NE];
__device__ int   g_perm[NPAIR];

// ---------------- helpers ----------------
__device__ __forceinline__ uint32_t pack_h2(float a, float b){
    __half2 h = __floats2half2_rn(a, b);
    return *reinterpret_cast<uint32_t*>(&h);
}
__device__ __forceinline__ void cp_async16(unsigned saddr, const void* g, int sz){
    asm volatile("cp.async.cg.shared.global [%0], [%1], 16, %2;\n"
                 :: "r"(saddr), "l"(g), "r"(sz));
}
__device__ __forceinline__ void cp_commit(){ asm volatile("cp.async.commit_group;\n"); }
template<int N>
__device__ __forceinline__ void cp_wait(){ asm volatile("cp.async.wait_group %0;\n"::"n"(N)); }
__device__ __forceinline__ void ldm_x4(uint32_t* r, uint32_t addr){
    asm volatile("ldmatrix.sync.aligned.m8n8.x4.shared.b16 {%0,%1,%2,%3}, [%4];"
                 : "=r"(r[0]), "=r"(r[1]), "=r"(r[2]), "=r"(r[3]) : "r"(addr));
}
__device__ __forceinline__ float2 lds64(uint32_t a){
    float2 r;
    asm volatile("ld.shared.v2.f32 {%0,%1}, [%2];" : "=f"(r.x), "=f"(r.y) : "r"(a));
    return r;
}
__device__ __forceinline__ void mma16(float* d, const uint32_t* a, const uint32_t* b){
    asm volatile("mma.sync.aligned.m16n8k16.row.col.f32.f16.f16.f32 "
                 "{%0,%1,%2,%3},{%4,%5,%6,%7},{%8,%9},{%0,%1,%2,%3};\n"
                 : "+f"(d[0]), "+f"(d[1]), "+f"(d[2]), "+f"(d[3])
                 : "r"(a[0]), "r"(a[1]), "r"(a[2]), "r"(a[3]),
                   "r"(b[0]), "r"(b[1]));
}

// ---------------- init: zero counters only ----------------
__global__ void init_kernel(){
    int i = threadIdx.x;
    if (i < NE) { g_cnt[i] = 0; g_pos[i] = 0; }
}

// ---------------- rmsnorm + residual copy + gate + top-4 + softmax ----------------
__global__ void route_kernel(const float* __restrict__ x,
                             const float* __restrict__ nscale,
                             const float* __restrict__ gw,
                             const float* __restrict__ gb,
                             float* __restrict__ out){
    int t  = blockIdx.x;
    int tx = threadIdx.x;
    __shared__ float sT[HD];
    __shared__ float sred[256];
    __shared__ float slog[NE];
    const float* xr = x + (size_t)t*HD;
    float* orow = out + (size_t)t*HD;

    float ss = 0.f;
    for (int i = tx; i < HD; i += 256){
        float v = xr[i];
        sT[i] = v;
        orow[i] = v;              // residual init
        ss += v*v;
    }
    sred[tx] = ss; __syncthreads();
    for (int s = 128; s > 0; s >>= 1){ if (tx < s) sred[tx] += sred[tx+s]; __syncthreads(); }
    float r = rsqrtf(sred[0]/(float)HD + 1e-5f);
    __syncthreads();
    for (int i = tx; i < HD; i += 256){
        float v = sT[i]*r*nscale[i];
        sT[i] = v;
        g_th[(size_t)t*HD + i] = __float2half_rn(v);
    }
    __syncthreads();

    int e  = (tx>>5)*4 + ((tx&31)>>3);
    int li = tx & 7;
    const float* gwr = gw + (size_t)e*HD;
    float p = 0.f;
    for (int i = li; i < HD; i += 8) p += sT[i]*gwr[i];
    p += __shfl_down_sync(0xffffffffu, p, 4, 8);
    p += __shfl_down_sync(0xffffffffu, p, 2, 8);
    p += __shfl_down_sync(0xffffffffu, p, 1, 8);
    if (li == 0) slog[e] = p + gb[e];
    __syncthreads();

    if (tx == 0){
        float l[NE];
        #pragma unroll
        for (int i = 0; i < NE; i++) l[i] = slog[i];
        float v[TOPK]; int id[TOPK];
        #pragma unroll
        for (int k = 0; k < TOPK; k++){
            float best = -1e30f; int bi = 0;
            for (int i = 0; i < NE; i++) if (l[i] > best){ best = l[i]; bi = i; }
            v[k] = best; id[k] = bi; l[bi] = -1e30f;
        }
        float m = v[0], s = 0.f, w4[TOPK];
        #pragma unroll
        for (int k = 0; k < TOPK; k++){ w4[k] = expf(v[k]-m); s += w4[k]; }
        float inv = 1.f/s;
        #pragma unroll
        for (int k = 0; k < TOPK; k++){
            int pr = t*TOPK + k;
            g_wt[pr]  = w4[k]*inv;
            g_eid[pr] = id[k];
            atomicAdd(&g_cnt[id[k]], 1);
        }
    }
}

// ---------------- scatter (in-block expert offsets) ----------------
__global__ void scatter_kernel(){
    __shared__ int soff[NE];
    if (threadIdx.x == 0){
        int off = 0;
        for (int e = 0; e < NE; e++){ soff[e] = off; off += g_cnt[e]; }
    }
    __syncthreads();
    int p = blockIdx.x*blockDim.x + threadIdx.x;
    if (p < NPAIR){
        int e = g_eid[p];
        int pos = soff[e] + atomicAdd(&g_pos[e], 1);
        g_perm[pos] = p;
    }
}

// ============ fp16-A / fp32-B grouped GEMM mainloop with M-skip ============
struct Frag { float acc[4][4][4]; };

__device__ __forceinline__ void gemm_mainloop(
    uint32_t smem0, const int* sPair, int rcnt,
    const __half* __restrict__ Asrc, int a_is_token,
    const float* __restrict__ W,
    Frag& fr, int tx)
{
    int lane = tx & 31, w = tx >> 5;
    int wm = w & 1, wn = w >> 1;
    int m0b = wm*64, n0b = wn*32;

    // number of active 16-row blocks for this warp (0..4)
    int mtmax = (rcnt - m0b + 15) >> 4;
    if (mtmax < 0) mtmax = 0;
    if (mtmax > 4) mtmax = 4;

    #pragma unroll
    for (int mt = 0; mt < 4; mt++)
        #pragma unroll
        for (int nt = 0; nt < 4; nt++)
            #pragma unroll
            for (int i = 0; i < 4; i++) fr.acc[mt][nt][i] = 0.f;

    // per-thread fill: 6 chunks of 16B.  chunks 0..511: A, 512..1535: B
    const char* srcp[6];
    uint32_t    dst0[6];
    int         szv[6];
    int         stepb[6];
    #pragma unroll
    for (int i = 0; i < 6; i++){
        int idx = tx + i*256;
        if (idx < 512){
            int row = idx >> 2, c = idx & 3;
            int p = sPair[row];
            int valid = (p >= 0);
            long arow = a_is_token ? (long)(p >> 2) : (long)p;
            srcp[i]  = (const char*)(Asrc + (valid ? arow*1024 : 0) + c*8);
            dst0[i]  = smem0 + row*A_ROWB + c*16;
            szv[i]   = valid ? 16 : 0;
            stepb[i] = BK*2;              // halves
        } else {
            int bidx = idx - 512;
            int row = bidx >> 3, c = bidx & 7;
            srcp[i]  = (const char*)(W + (size_t)row*1024 + c*4);
            dst0[i]  = smem0 + A_TILE_B + row*B_ROWB + c*16;
            szv[i]   = 16;
            stepb[i] = BK*4;              // floats
        }
    }

    // ldmatrix A base: row = m0 + (lane&15), 16B chunk = lane>>4
    uint32_t aAddr = smem0 + (m0b + (lane & 15))*A_ROWB + (lane >> 4)*16;
    // B fp32 base: n = n0 + (lane>>2), k pair = (lane&3)*2 floats
    uint32_t bAddr = smem0 + A_TILE_B + (n0b + (lane >> 2))*B_ROWB + (lane & 3)*8;

    // prologue: stages 0,1
    #pragma unroll
    for (int f = 0; f < NSTAGE-1; f++){
        #pragma unroll
        for (int i = 0; i < 6; i++)
            cp_async16(dst0[i] + f*STAGE_B, srcp[i] + (size_t)f*stepb[i], szv[i]);
        cp_commit();
    }

    int s_use = 0, s_fill = NSTAGE-1;
    for (int it = 0; it < NIT; it++){
        cp_wait<NSTAGE-2>();
        __syncthreads();

        uint32_t off = s_use*STAGE_B;

        if (mtmax > 0){
            // B fragments: fp32 -> fp16 in register
            uint32_t bfr[4][2][2];
            #pragma unroll
            for (int nt = 0; nt < 4; nt++){
                #pragma unroll
                for (int ks = 0; ks < 2; ks++){
                    uint32_t ba = bAddr + off + nt*(8*B_ROWB) + ks*64;
                    float2 f0 = lds64(ba);
                    float2 f1 = lds64(ba + 32);
                    bfr[nt][ks][0] = pack_h2(f0.x, f0.y);
                    bfr[nt][ks][1] = pack_h2(f1.x, f1.y);
                }
            }
            #pragma unroll
            for (int ks = 0; ks < 2; ks++){
                #pragma unroll
                for (int mt = 0; mt < 4; mt++){
                    if (mt < mtmax){
                        uint32_t afr[4];
                        ldm_x4(afr, aAddr + off + mt*(16*A_ROWB) + ks*32);
                        #pragma unroll
                        for (int nt = 0; nt < 4; nt++)
                            mma16(fr.acc[mt][nt], afr, bfr[nt][ks]);
                    }
                }
            }
        }

        int f = it + NSTAGE - 1;
        if (f < NIT){
            uint32_t doff = s_fill*STAGE_B;
            #pragma unroll
            for (int i = 0; i < 6; i++)
                cp_async16(dst0[i] + doff, srcp[i] + (size_t)f*stepb[i], szv[i]);
        }
        cp_commit();
        s_use  = (s_use  + 1 == NSTAGE) ? 0 : s_use  + 1;
        s_fill = (s_fill + 1 == NSTAGE) ? 0 : s_fill + 1;
    }
}

// ---------------- per-block tile lookup ----------------
__device__ __forceinline__ void tile_info(int mt_, int* sInfo, int tx){
    if (tx == 0){
        int off = 0, nt = 0, te = -1, trow = 0, tcnt = 0;
        for (int e = 0; e < NE; e++){
            int c = g_cnt[e];
            for (int r = 0; r < c; r += BM){
                if (nt == mt_){ te = e; trow = off + r; tcnt = min(BM, c - r); }
                nt++;
            }
            off += c;
        }
        sInfo[0] = te; sInfo[1] = trow; sInfo[2] = tcnt;
    }
}

// ---------------- mlp1: grouped GEMM + swiglu ----------------
__global__ __launch_bounds__(256, 2) void mlp1_kernel(const float* __restrict__ w1,
                                                      const float* __restrict__ b1){
    __shared__ int   sInfo[3];
    __shared__ int   sPair[BM];
    __shared__ float sWgt[BM];
    extern __shared__ char dsm[];
    uint32_t smem0 = (uint32_t)__cvta_generic_to_shared(dsm);

    int tx = threadIdx.x;
    tile_info(blockIdx.x, sInfo, tx);
    __syncthreads();
    int e = sInfo[0];
    if (e < 0) return;
    int rowstart = sInfo[1], rcnt = sInfo[2];
    int nb = blockIdx.y;

    if (tx < BM){
        int p = (tx < rcnt) ? g_perm[rowstart + tx] : -1;
        sPair[tx] = p;
        sWgt[tx]  = (p >= 0) ? g_wt[p] : 0.f;
    }
    __syncthreads();

    const float* W = w1 + (size_t)e*(2*FD)*HD + (size_t)(nb*BN)*HD;
    Frag fr;
    gemm_mainloop(smem0, sPair, rcnt, g_th, 1, W, fr, tx);

    int w  = tx >> 5, lane = tx & 31;
    int g  = lane >> 2, t4 = lane & 3;
    int wm = w & 1, wn = w >> 1;
    const float* b1e = b1 + (size_t)e*(2*FD);

    #pragma unroll
    for (int nt = 0; nt < 4; nt++){
        int colb = nb*BN + wn*32 + nt*8 + 2*t4;      // even
        float bg = b1e[colb], bl = b1e[colb+1];
        int f = colb >> 1;
        #pragma unroll
        for (int mt = 0; mt < 4; mt++){
            #pragma unroll
            for (int half = 0; half < 2; half++){
                int row = wm*64 + mt*16 + g + half*8;
                int p = sPair[row];
                if (p < 0) continue;
                float wg = sWgt[row];
                float d0 = fr.acc[mt][nt][2*half+0] + bg;
                float d1 = fr.acc[mt][nt][2*half+1] + bl;
                float glu = fminf(d0, 7.0f);
                float lin = fminf(fmaxf(d1, -7.0f), 7.0f);
                float sg  = 1.f/(1.f + expf(-1.702f*glu));
                g_acth[(size_t)p*FD + f] = __float2half_rn(glu*sg*(lin + 1.f)*wg);
            }
        }
    }
}

// ---------------- mlp2: grouped GEMM + scatter-add ----------------
__global__ __launch_bounds__(256, 2) void mlp2_kernel(const float* __restrict__ w2,
                                                      const float* __restrict__ b2,
                                                      float* __restrict__ out){
    __shared__ int   sInfo[3];
    __shared__ int   sPair[BM];
    __shared__ float sWgt[BM];
    extern __shared__ char dsm[];
    uint32_t smem0 = (uint32_t)__cvta_generic_to_shared(dsm);

    int tx = threadIdx.x;
    tile_info(blockIdx.x, sInfo, tx);
    __syncthreads();
    int e = sInfo[0];
    if (e < 0) return;
    int rowstart = sInfo[1], rcnt = sInfo[2];
    int nb = blockIdx.y;

    if (tx < BM){
        int p = (tx < rcnt) ? g_perm[rowstart + tx] : -1;
        sPair[tx] = p;
        sWgt[tx]  = (p >= 0) ? g_wt[p] : 0.f;
    }
    __syncthreads();

    const float* W = w2 + (size_t)e*HD*FD + (size_t)(nb*BN)*FD;
    Frag fr;
    gemm_mainloop(smem0, sPair, rcnt, g_acth, 0, W, fr, tx);

    int w  = tx >> 5, lane = tx & 31;
    int g  = lane >> 2, t4 = lane & 3;
    int wm = w & 1, wn = w >> 1;
    const float* b2e = b2 + (size_t)e*HD;

    #pragma unroll
    for (int nt = 0; nt < 4; nt++){
        int colb = nb*BN + wn*32 + nt*8 + 2*t4;
        float bb0 = b2e[colb], bb1 = b2e[colb+1];
        #pragma unroll
        for (int mt = 0; mt < 4; mt++){
            #pragma unroll
            for (int half = 0; half < 2; half++){
                int row = wm*64 + mt*16 + g + half*8;
                int p = sPair[row];
                if (p < 0) continue;
                int tok = p >> 2;
                float wg = sWgt[row];
                float* o = out + (size_t)tok*HD + colb;
                atomicAdd(o,     fr.acc[mt][nt][2*half+0] + wg*bb0);
                atomicAdd(o + 1, fr.acc[mt][nt][2*half+1] + wg*bb1);
            }
        }
    }
}

// ---------------- launch ----------------
extern "C" void kernel_launch(void* const* d_in, const int* in_sizes, int n_in,
                              void* d_out, int out_size){
    const float* x      = (const float*)d_in[0];
    const float* nscale = (const float*)d_in[1];
    const float* gw     = (const float*)d_in[2];
    const float* gb     = (const float*)d_in[3];
    const float* w1     = (const float*)d_in[4];
    const float* b1     = (const float*)d_in[5];
    const float* w2     = (const float*)d_in[6];
    const float* b2     = (const float*)d_in[7];
    float* out = (float*)d_out;

    const int smem_bytes = NSTAGE*STAGE_B;      // 92160
    static int configured = 0;
    if (!configured){
        cudaFuncSetAttribute(mlp1_kernel, cudaFuncAttributeMaxDynamicSharedMemorySize, smem_bytes);
        cudaFuncSetAttribute(mlp2_kernel, cudaFuncAttributeMaxDynamicSharedMemorySize, smem_bytes);
        configured = 1;
    }

    init_kernel   <<<1, 64>>>();
    route_kernel  <<<T, 256>>>(x, nscale, gw, gb, out);
    scatter_kernel<<<(NPAIR + 255)/256, 256>>>();
    mlp1_kernel   <<<dim3(MT_MAX, (2*FD)/BN), 256, smem_bytes>>>(w1, b1);
    mlp2_kernel   <<<dim3(MT_MAX, HD/BN),     256, smem_bytes>>>(w2, b2, out);
}